// round 2
// baseline (speedup 1.0000x reference)
#include <cuda_runtime.h>
#include <math.h>

#define NN 384
#define CC 128
#define HH 4
#define DD 32
#define MM (NN*NN)

// Scratch (allocation-free: __device__ globals)
__device__ float d_x[(size_t)MM*CC];      // layernormed pair
__device__ float d_y[(size_t)MM*512];     // [q|k|v|g] concatenated, q pre-scaled
__device__ float d_bias[(size_t)HH*MM];   // bias[h, q, k]
__device__ float d_o[(size_t)MM*CC];      // attention output [b,n,h*32+d]

// ---------------------------------------------------------------------------
// Kernel 1: LayerNorm + pair bias. One warp per row (128 channels, 4/lane).
// ---------------------------------------------------------------------------
__global__ __launch_bounds__(256) void ln_bias_kernel(
    const float* __restrict__ pair,
    const float* __restrict__ ln_w,
    const float* __restrict__ ln_b,
    const float* __restrict__ w_bias)
{
    int warp = threadIdx.x >> 5, lane = threadIdx.x & 31;
    int r = blockIdx.x * 8 + warp;
    if (r >= MM) return;

    float4 v = ((const float4*)(pair + (size_t)r * CC))[lane];
    float s  = v.x + v.y + v.z + v.w;
    float sq = v.x*v.x + v.y*v.y + v.z*v.z + v.w*v.w;
    #pragma unroll
    for (int o = 16; o; o >>= 1) {
        s  += __shfl_xor_sync(0xffffffffu, s,  o);
        sq += __shfl_xor_sync(0xffffffffu, sq, o);
    }
    float mean = s * (1.0f / CC);
    float var  = sq * (1.0f / CC) - mean * mean;
    float inv  = rsqrtf(var + 1e-5f);

    float4 w = ((const float4*)ln_w)[lane];
    float4 b = ((const float4*)ln_b)[lane];
    float4 xn;
    xn.x = (v.x - mean) * inv * w.x + b.x;
    xn.y = (v.y - mean) * inv * w.y + b.y;
    xn.z = (v.z - mean) * inv * w.z + b.z;
    xn.w = (v.w - mean) * inv * w.w + b.w;
    ((float4*)(d_x + (size_t)r * CC))[lane] = xn;

    // bias[h] = sum_c xn_c * w_bias[c, h]   (w_bias row-major [C,H], H=4)
    float accb0 = 0.f, accb1 = 0.f, accb2 = 0.f, accb3 = 0.f;
    float xv[4] = {xn.x, xn.y, xn.z, xn.w};
    #pragma unroll
    for (int i = 0; i < 4; i++) {
        float4 wb = ((const float4*)w_bias)[lane * 4 + i];
        accb0 += xv[i] * wb.x;
        accb1 += xv[i] * wb.y;
        accb2 += xv[i] * wb.z;
        accb3 += xv[i] * wb.w;
    }
    #pragma unroll
    for (int o = 16; o; o >>= 1) {
        accb0 += __shfl_xor_sync(0xffffffffu, accb0, o);
        accb1 += __shfl_xor_sync(0xffffffffu, accb1, o);
        accb2 += __shfl_xor_sync(0xffffffffu, accb2, o);
        accb3 += __shfl_xor_sync(0xffffffffu, accb3, o);
    }
    if (lane == 0) {
        d_bias[(size_t)0 * MM + r] = accb0;
        d_bias[(size_t)1 * MM + r] = accb1;
        d_bias[(size_t)2 * MM + r] = accb2;
        d_bias[(size_t)3 * MM + r] = accb3;
    }
}

// ---------------------------------------------------------------------------
// Kernel 2: projections Y[M,512] = X[M,128] @ [wq|wk|wv|wg]. 64x64x64 tiles,
// 256 threads, 4x4 per thread. q columns (j<128) pre-scaled by D^-0.5.
// ---------------------------------------------------------------------------
__global__ __launch_bounds__(256) void proj_gemm(
    const float* __restrict__ wq, const float* __restrict__ wk,
    const float* __restrict__ wv, const float* __restrict__ wg)
{
    __shared__ float As[64][64];
    __shared__ float Bs[64][64];

    int m0 = blockIdx.x * 64;
    int jb = blockIdx.y * 64;          // global output column base (0..448)
    int sel = jb >> 7;
    const float* w = (sel == 0) ? wq : (sel == 1) ? wk : (sel == 2) ? wv : wg;
    int jbase = jb & 127;              // column base within the selected matrix

    int tx = threadIdx.x & 15, ty = threadIdx.x >> 4;
    float acc[4][4] = {};

    for (int kk = 0; kk < 128; kk += 64) {
        #pragma unroll
        for (int i = 0; i < 4; i++) {
            int idx = threadIdx.x + i * 256;
            int row = idx >> 4, c4 = (idx & 15) * 4;
            *(float4*)&As[row][c4] =
                *(const float4*)&d_x[(size_t)(m0 + row) * 128 + kk + c4];
            *(float4*)&Bs[row][c4] =
                *(const float4*)&w[(size_t)(kk + row) * 128 + jbase + c4];
        }
        __syncthreads();
        #pragma unroll 8
        for (int k = 0; k < 64; k++) {
            float4 b4 = *(float4*)&Bs[k][tx * 4];
            float a0 = As[ty*4+0][k], a1 = As[ty*4+1][k];
            float a2 = As[ty*4+2][k], a3 = As[ty*4+3][k];
            acc[0][0] += a0*b4.x; acc[0][1] += a0*b4.y; acc[0][2] += a0*b4.z; acc[0][3] += a0*b4.w;
            acc[1][0] += a1*b4.x; acc[1][1] += a1*b4.y; acc[1][2] += a1*b4.z; acc[1][3] += a1*b4.w;
            acc[2][0] += a2*b4.x; acc[2][1] += a2*b4.y; acc[2][2] += a2*b4.z; acc[2][3] += a2*b4.w;
            acc[3][0] += a3*b4.x; acc[3][1] += a3*b4.y; acc[3][2] += a3*b4.z; acc[3][3] += a3*b4.w;
        }
        __syncthreads();
    }

    float scale = (sel == 0) ? 0.17677669529663687f : 1.0f;  // D^-0.5 for q
    #pragma unroll
    for (int i = 0; i < 4; i++) {
        float4 r;
        r.x = acc[i][0] * scale; r.y = acc[i][1] * scale;
        r.z = acc[i][2] * scale; r.w = acc[i][3] * scale;
        *(float4*)&d_y[(size_t)(m0 + ty*4 + i) * 512 + jb + tx*4] = r;
    }
}

// ---------------------------------------------------------------------------
// Kernel 3: attention per (b,h). K/V staged in smem (stride 33, bank-safe).
// 1024 threads = 32 warps; each warp owns query rows qi = warp, warp+32, ...
// mask is int32 (bool input delivered as int32 by the harness).
// ---------------------------------------------------------------------------
#define ATTN_SMEM_FLOATS (2*NN*33 + 32*NN + 32*32)

__global__ __launch_bounds__(1024) void attn_kernel(const int* __restrict__ mask)
{
    extern __shared__ float sm[];
    float* Ks = sm;                   // [384][33]
    float* Vs = sm + NN * 33;         // [384][33]
    float* Ps = Vs + NN * 33;         // [32 warps][384]
    float* Qs = Ps + 32 * NN;         // [32 warps][32]

    int b = blockIdx.x, h = blockIdx.y;
    int tid = threadIdx.x, lane = tid & 31, warp = tid >> 5;
    const float* Yb = d_y + (size_t)b * NN * 512;

    for (int idx = tid; idx < NN * 32; idx += 1024) {
        int n = idx >> 5, d = idx & 31;
        Ks[n * 33 + d] = Yb[(size_t)n * 512 + 128 + h * 32 + d];
        Vs[n * 33 + d] = Yb[(size_t)n * 512 + 256 + h * 32 + d];
    }
    __syncthreads();

    float* ps  = Ps + warp * NN;
    float* qsw = Qs + warp * 32;
    const int* mrow = mask + (size_t)b * NN;

    for (int qi = warp; qi < NN; qi += 32) {
        qsw[lane] = Yb[(size_t)qi * 512 + h * 32 + lane];  // q already scaled
        __syncwarp();

        const float* biasrow = d_bias + (size_t)h * MM + (size_t)qi * NN;
        float lg[12];
        float mx = -1e30f;
        #pragma unroll
        for (int i = 0; i < 12; i++) {
            int k = i * 32 + lane;
            const float* Kr = Ks + k * 33;
            float acc = 0.f;
            #pragma unroll
            for (int d = 0; d < 32; d++) acc += qsw[d] * Kr[d];
            acc += biasrow[k];
            if (mrow[k] == 0) acc = -1e9f;
            lg[i] = acc;
            mx = fmaxf(mx, acc);
        }
        #pragma unroll
        for (int o = 16; o; o >>= 1) mx = fmaxf(mx, __shfl_xor_sync(0xffffffffu, mx, o));

        float sum = 0.f;
        #pragma unroll
        for (int i = 0; i < 12; i++) { float e = __expf(lg[i] - mx); lg[i] = e; sum += e; }
        #pragma unroll
        for (int o = 16; o; o >>= 1) sum += __shfl_xor_sync(0xffffffffu, sum, o);
        float invs = 1.f / sum;

        #pragma unroll
        for (int i = 0; i < 12; i++) ps[i * 32 + lane] = lg[i] * invs;
        __syncwarp();

        float acc = 0.f;
        #pragma unroll 4
        for (int k = 0; k < NN; k++) acc += ps[k] * Vs[k * 33 + lane];
        d_o[((size_t)b * NN + qi) * CC + h * 32 + lane] = acc;
        __syncwarp();
    }
}

// ---------------------------------------------------------------------------
// Kernel 4: out = (o * sigmoid(g)) @ wo. Gate fused into A-tile load.
// ---------------------------------------------------------------------------
__global__ __launch_bounds__(256) void out_gemm(
    const float* __restrict__ wo, float* __restrict__ out)
{
    __shared__ float As[64][64];
    __shared__ float Bs[64][64];

    int m0 = blockIdx.x * 64;
    int n0 = blockIdx.y * 64;
    int tx = threadIdx.x & 15, ty = threadIdx.x >> 4;
    float acc[4][4] = {};

    for (int kk = 0; kk < 128; kk += 64) {
        #pragma unroll
        for (int i = 0; i < 4; i++) {
            int idx = threadIdx.x + i * 256;
            int row = idx >> 4, c4 = (idx & 15) * 4;
            float4 ov = *(const float4*)&d_o[(size_t)(m0 + row) * 128 + kk + c4];
            float4 gv = *(const float4*)&d_y[(size_t)(m0 + row) * 512 + 384 + kk + c4];
            float4 a;
            a.x = ov.x * (1.f / (1.f + __expf(-gv.x)));
            a.y = ov.y * (1.f / (1.f + __expf(-gv.y)));
            a.z = ov.z * (1.f / (1.f + __expf(-gv.z)));
            a.w = ov.w * (1.f / (1.f + __expf(-gv.w)));
            *(float4*)&As[row][c4] = a;
            *(float4*)&Bs[row][c4] =
                *(const float4*)&wo[(size_t)(kk + row) * 128 + n0 + c4];
        }
        __syncthreads();
        #pragma unroll 8
        for (int k = 0; k < 64; k++) {
            float4 b4 = *(float4*)&Bs[k][tx * 4];
            float a0 = As[ty*4+0][k], a1 = As[ty*4+1][k];
            float a2 = As[ty*4+2][k], a3 = As[ty*4+3][k];
            acc[0][0] += a0*b4.x; acc[0][1] += a0*b4.y; acc[0][2] += a0*b4.z; acc[0][3] += a0*b4.w;
            acc[1][0] += a1*b4.x; acc[1][1] += a1*b4.y; acc[1][2] += a1*b4.z; acc[1][3] += a1*b4.w;
            acc[2][0] += a2*b4.x; acc[2][1] += a2*b4.y; acc[2][2] += a2*b4.z; acc[2][3] += a2*b4.w;
            acc[3][0] += a3*b4.x; acc[3][1] += a3*b4.y; acc[3][2] += a3*b4.z; acc[3][3] += a3*b4.w;
        }
        __syncthreads();
    }

    #pragma unroll
    for (int i = 0; i < 4; i++) {
        float4 r;
        r.x = acc[i][0]; r.y = acc[i][1]; r.z = acc[i][2]; r.w = acc[i][3];
        *(float4*)&out[(size_t)(m0 + ty*4 + i) * 128 + n0 + tx*4] = r;
    }
}

// ---------------------------------------------------------------------------
extern "C" void kernel_launch(void* const* d_in, const int* in_sizes, int n_in,
                              void* d_out, int out_size)
{
    const float* pair   = (const float*)d_in[0];
    const int*   mask   = (const int*)d_in[1];
    const float* ln_w   = (const float*)d_in[2];
    const float* ln_b   = (const float*)d_in[3];
    const float* w_bias = (const float*)d_in[4];
    const float* wq     = (const float*)d_in[5];
    const float* wk     = (const float*)d_in[6];
    const float* wv     = (const float*)d_in[7];
    const float* wg     = (const float*)d_in[8];
    const float* wo     = (const float*)d_in[9];
    float* out = (float*)d_out;

    (void)in_sizes; (void)n_in; (void)out_size;

    ln_bias_kernel<<<MM / 8, 256>>>(pair, ln_w, ln_b, w_bias);
    proj_gemm<<<dim3(MM / 64, 8), 256>>>(wq, wk, wv, wg);

    size_t attn_smem = (size_t)ATTN_SMEM_FLOATS * sizeof(float);
    cudaFuncSetAttribute(attn_kernel,
                         cudaFuncAttributeMaxDynamicSharedMemorySize,
                         (int)attn_smem);
    attn_kernel<<<dim3(NN, HH), 1024, attn_smem>>>(mask);

    out_gemm<<<dim3(MM / 64, 2), 256>>>(wo, out);
}

// round 3
// speedup vs baseline: 1.5665x; 1.5665x over previous
#include <cuda_runtime.h>
#include <math.h>

#define NN 384
#define CC 128
#define HH 4
#define DD 32
#define MM (NN*NN)

// Scratch (allocation-free: __device__ globals)
__device__ float d_x[(size_t)MM*CC];      // layernormed pair
__device__ float d_y[(size_t)MM*512];     // [q|k|v|g] concatenated, q pre-scaled
__device__ float d_bias[(size_t)HH*MM];   // bias[h, q, k]
__device__ float d_o[(size_t)MM*CC];      // attention output [b,n,h*32+d]

// ---------------------------------------------------------------------------
// Kernel 1: LayerNorm + pair bias. One warp per row (128 channels, 4/lane).
// ---------------------------------------------------------------------------
__global__ __launch_bounds__(256) void ln_bias_kernel(
    const float* __restrict__ pair,
    const float* __restrict__ ln_w,
    const float* __restrict__ ln_b,
    const float* __restrict__ w_bias)
{
    int warp = threadIdx.x >> 5, lane = threadIdx.x & 31;
    int r = blockIdx.x * 8 + warp;
    if (r >= MM) return;

    float4 v = ((const float4*)(pair + (size_t)r * CC))[lane];
    float s  = v.x + v.y + v.z + v.w;
    float sq = v.x*v.x + v.y*v.y + v.z*v.z + v.w*v.w;
    #pragma unroll
    for (int o = 16; o; o >>= 1) {
        s  += __shfl_xor_sync(0xffffffffu, s,  o);
        sq += __shfl_xor_sync(0xffffffffu, sq, o);
    }
    float mean = s * (1.0f / CC);
    float var  = sq * (1.0f / CC) - mean * mean;
    float inv  = rsqrtf(var + 1e-5f);

    float4 w = ((const float4*)ln_w)[lane];
    float4 b = ((const float4*)ln_b)[lane];
    float4 xn;
    xn.x = (v.x - mean) * inv * w.x + b.x;
    xn.y = (v.y - mean) * inv * w.y + b.y;
    xn.z = (v.z - mean) * inv * w.z + b.z;
    xn.w = (v.w - mean) * inv * w.w + b.w;
    ((float4*)(d_x + (size_t)r * CC))[lane] = xn;

    // bias[h] = sum_c xn_c * w_bias[c, h]   (w_bias row-major [C,H], H=4)
    float accb0 = 0.f, accb1 = 0.f, accb2 = 0.f, accb3 = 0.f;
    float xv[4] = {xn.x, xn.y, xn.z, xn.w};
    #pragma unroll
    for (int i = 0; i < 4; i++) {
        float4 wb = ((const float4*)w_bias)[lane * 4 + i];
        accb0 += xv[i] * wb.x;
        accb1 += xv[i] * wb.y;
        accb2 += xv[i] * wb.z;
        accb3 += xv[i] * wb.w;
    }
    #pragma unroll
    for (int o = 16; o; o >>= 1) {
        accb0 += __shfl_xor_sync(0xffffffffu, accb0, o);
        accb1 += __shfl_xor_sync(0xffffffffu, accb1, o);
        accb2 += __shfl_xor_sync(0xffffffffu, accb2, o);
        accb3 += __shfl_xor_sync(0xffffffffu, accb3, o);
    }
    if (lane == 0) {
        d_bias[(size_t)0 * MM + r] = accb0;
        d_bias[(size_t)1 * MM + r] = accb1;
        d_bias[(size_t)2 * MM + r] = accb2;
        d_bias[(size_t)3 * MM + r] = accb3;
    }
}

// ---------------------------------------------------------------------------
// Kernel 2: projections Y[M,512] = X[M,128] @ [wq|wk|wv|wg]. 64x64x64 tiles.
// ---------------------------------------------------------------------------
__global__ __launch_bounds__(256) void proj_gemm(
    const float* __restrict__ wq, const float* __restrict__ wk,
    const float* __restrict__ wv, const float* __restrict__ wg)
{
    __shared__ float As[64][64];
    __shared__ float Bs[64][64];

    int m0 = blockIdx.x * 64;
    int jb = blockIdx.y * 64;
    int sel = jb >> 7;
    const float* w = (sel == 0) ? wq : (sel == 1) ? wk : (sel == 2) ? wv : wg;
    int jbase = jb & 127;

    int tx = threadIdx.x & 15, ty = threadIdx.x >> 4;
    float acc[4][4] = {};

    for (int kk = 0; kk < 128; kk += 64) {
        #pragma unroll
        for (int i = 0; i < 4; i++) {
            int idx = threadIdx.x + i * 256;
            int row = idx >> 4, c4 = (idx & 15) * 4;
            *(float4*)&As[row][c4] =
                *(const float4*)&d_x[(size_t)(m0 + row) * 128 + kk + c4];
            *(float4*)&Bs[row][c4] =
                *(const float4*)&w[(size_t)(kk + row) * 128 + jbase + c4];
        }
        __syncthreads();
        #pragma unroll 8
        for (int k = 0; k < 64; k++) {
            float4 b4 = *(float4*)&Bs[k][tx * 4];
            float a0 = As[ty*4+0][k], a1 = As[ty*4+1][k];
            float a2 = As[ty*4+2][k], a3 = As[ty*4+3][k];
            acc[0][0] += a0*b4.x; acc[0][1] += a0*b4.y; acc[0][2] += a0*b4.z; acc[0][3] += a0*b4.w;
            acc[1][0] += a1*b4.x; acc[1][1] += a1*b4.y; acc[1][2] += a1*b4.z; acc[1][3] += a1*b4.w;
            acc[2][0] += a2*b4.x; acc[2][1] += a2*b4.y; acc[2][2] += a2*b4.z; acc[2][3] += a2*b4.w;
            acc[3][0] += a3*b4.x; acc[3][1] += a3*b4.y; acc[3][2] += a3*b4.z; acc[3][3] += a3*b4.w;
        }
        __syncthreads();
    }

    float scale = (sel == 0) ? 0.17677669529663687f : 1.0f;
    #pragma unroll
    for (int i = 0; i < 4; i++) {
        float4 r;
        r.x = acc[i][0] * scale; r.y = acc[i][1] * scale;
        r.z = acc[i][2] * scale; r.w = acc[i][3] * scale;
        *(float4*)&d_y[(size_t)(m0 + ty*4 + i) * 512 + jb + tx*4] = r;
    }
}

// ---------------------------------------------------------------------------
// Kernel 3: attention per (b,h), register-blocked.
// 512 threads = 16 warps; each warp owns 24 queries in 6 groups of 4.
// Phase A: acc[4][12] register tile (3:1 FFMA:LDS).
// Phase B: V transposed in smem [32][388] (conflict-free float4), P warp-private.
// ---------------------------------------------------------------------------
#define SM_KS   0                       // [384][33] = 12672
#define SM_VT   12672                   // [32][388] = 12416
#define SM_MSK  25088                   // [384]
#define SM_QS   25472                   // [16][4*33] = 2112
#define SM_PS   27584                   // [16][4*388] = 24832
#define ATTN_SMEM_FLOATS 52416

__global__ __launch_bounds__(512) void attn_kernel(const int* __restrict__ mask)
{
    extern __shared__ float sm[];
    float* Ks  = sm + SM_KS;
    float* Vt  = sm + SM_VT;
    float* Msk = sm + SM_MSK;

    int b = blockIdx.x, h = blockIdx.y;
    int tid = threadIdx.x, lane = tid & 31, w = tid >> 5;
    const float* Yb = d_y + (size_t)b * (NN * 512);

    // Stage K (row-major, stride 33) and V transposed (Vt[d][k], stride 388)
    for (int idx = tid; idx < NN * 32; idx += 512) {
        int n = idx >> 5, d = idx & 31;
        Ks[n * 33 + d]  = Yb[(size_t)n * 512 + 128 + h * 32 + d];
        Vt[d * 388 + n] = Yb[(size_t)n * 512 + 256 + h * 32 + d];
    }
    for (int k = tid; k < NN; k += 512)
        Msk[k] = (mask[(size_t)b * NN + k] != 0) ? 1.0f : 0.0f;
    __syncthreads();

    float* qs = sm + SM_QS + w * (4 * 33);
    float* ps = sm + SM_PS + w * (4 * 388);

    for (int g = 0; g < 6; g++) {
        int q0 = (g * 16 + w) * 4;

        // Load 4 query rows (already scaled by D^-0.5)
        #pragma unroll
        for (int j = 0; j < 4; j++)
            qs[j * 33 + lane] = Yb[(size_t)(q0 + j) * 512 + h * 32 + lane];
        __syncwarp();

        // Phase A: S[4][384] ; lane covers keys k = i*32 + lane
        float acc[4][12];
        #pragma unroll
        for (int j = 0; j < 4; j++)
            #pragma unroll
            for (int i = 0; i < 12; i++) acc[j][i] = 0.f;

        #pragma unroll 8
        for (int d = 0; d < 32; d++) {
            float kv[12];
            #pragma unroll
            for (int i = 0; i < 12; i++)
                kv[i] = Ks[(i * 32 + lane) * 33 + d];
            #pragma unroll
            for (int j = 0; j < 4; j++) {
                float qv = qs[j * 33 + d];
                #pragma unroll
                for (int i = 0; i < 12; i++) acc[j][i] += qv * kv[i];
            }
        }

        // Bias + mask + softmax (normalization deferred to output)
        float inv[4];
        #pragma unroll
        for (int j = 0; j < 4; j++) {
            const float* br = d_bias + (size_t)h * MM + (size_t)(q0 + j) * NN;
            float s[12];
            float mx = -1e30f;
            #pragma unroll
            for (int i = 0; i < 12; i++) {
                int k = i * 32 + lane;
                float v = acc[j][i] + br[k];
                v = (Msk[k] != 0.f) ? v : -1e9f;
                s[i] = v;
                mx = fmaxf(mx, v);
            }
            #pragma unroll
            for (int o = 16; o; o >>= 1)
                mx = fmaxf(mx, __shfl_xor_sync(0xffffffffu, mx, o));
            float sum = 0.f;
            #pragma unroll
            for (int i = 0; i < 12; i++) {
                float e = __expf(s[i] - mx);
                s[i] = e;
                sum += e;
            }
            #pragma unroll
            for (int o = 16; o; o >>= 1)
                sum += __shfl_xor_sync(0xffffffffu, sum, o);
            inv[j] = 1.f / sum;
            #pragma unroll
            for (int i = 0; i < 12; i++)
                ps[j * 388 + i * 32 + lane] = s[i];
        }
        __syncwarp();

        // Phase B: O[4][32] = P[4][384] @ V[384][32]; lane = output dim d
        float o0 = 0.f, o1 = 0.f, o2 = 0.f, o3 = 0.f;
        const float* vrow = Vt + lane * 388;
        #pragma unroll 4
        for (int kq = 0; kq < 96; kq++) {
            float4 v  = *(const float4*)&vrow[kq * 4];
            float4 p0 = *(const float4*)&ps[0 * 388 + kq * 4];
            float4 p1 = *(const float4*)&ps[1 * 388 + kq * 4];
            float4 p2 = *(const float4*)&ps[2 * 388 + kq * 4];
            float4 p3 = *(const float4*)&ps[3 * 388 + kq * 4];
            o0 += p0.x * v.x + p0.y * v.y + p0.z * v.z + p0.w * v.w;
            o1 += p1.x * v.x + p1.y * v.y + p1.z * v.z + p1.w * v.w;
            o2 += p2.x * v.x + p2.y * v.y + p2.z * v.z + p2.w * v.w;
            o3 += p3.x * v.x + p3.y * v.y + p3.z * v.z + p3.w * v.w;
        }
        float* ob = d_o + ((size_t)b * NN + q0) * CC + h * 32 + lane;
        ob[0 * CC] = o0 * inv[0];
        ob[1 * CC] = o1 * inv[1];
        ob[2 * CC] = o2 * inv[2];
        ob[3 * CC] = o3 * inv[3];
        __syncwarp();
    }
}

// ---------------------------------------------------------------------------
// Kernel 4: out = (o * sigmoid(g)) @ wo. Gate fused into A-tile load.
// ---------------------------------------------------------------------------
__global__ __launch_bounds__(256) void out_gemm(
    const float* __restrict__ wo, float* __restrict__ out)
{
    __shared__ float As[64][64];
    __shared__ float Bs[64][64];

    int m0 = blockIdx.x * 64;
    int n0 = blockIdx.y * 64;
    int tx = threadIdx.x & 15, ty = threadIdx.x >> 4;
    float acc[4][4] = {};

    for (int kk = 0; kk < 128; kk += 64) {
        #pragma unroll
        for (int i = 0; i < 4; i++) {
            int idx = threadIdx.x + i * 256;
            int row = idx >> 4, c4 = (idx & 15) * 4;
            float4 ov = *(const float4*)&d_o[(size_t)(m0 + row) * 128 + kk + c4];
            float4 gv = *(const float4*)&d_y[(size_t)(m0 + row) * 512 + 384 + kk + c4];
            float4 a;
            a.x = ov.x * (1.f / (1.f + __expf(-gv.x)));
            a.y = ov.y * (1.f / (1.f + __expf(-gv.y)));
            a.z = ov.z * (1.f / (1.f + __expf(-gv.z)));
            a.w = ov.w * (1.f / (1.f + __expf(-gv.w)));
            *(float4*)&As[row][c4] = a;
            *(float4*)&Bs[row][c4] =
                *(const float4*)&wo[(size_t)(kk + row) * 128 + n0 + c4];
        }
        __syncthreads();
        #pragma unroll 8
        for (int k = 0; k < 64; k++) {
            float4 b4 = *(float4*)&Bs[k][tx * 4];
            float a0 = As[ty*4+0][k], a1 = As[ty*4+1][k];
            float a2 = As[ty*4+2][k], a3 = As[ty*4+3][k];
            acc[0][0] += a0*b4.x; acc[0][1] += a0*b4.y; acc[0][2] += a0*b4.z; acc[0][3] += a0*b4.w;
            acc[1][0] += a1*b4.x; acc[1][1] += a1*b4.y; acc[1][2] += a1*b4.z; acc[1][3] += a1*b4.w;
            acc[2][0] += a2*b4.x; acc[2][1] += a2*b4.y; acc[2][2] += a2*b4.z; acc[2][3] += a2*b4.w;
            acc[3][0] += a3*b4.x; acc[3][1] += a3*b4.y; acc[3][2] += a3*b4.z; acc[3][3] += a3*b4.w;
        }
        __syncthreads();
    }

    #pragma unroll
    for (int i = 0; i < 4; i++) {
        float4 r;
        r.x = acc[i][0]; r.y = acc[i][1]; r.z = acc[i][2]; r.w = acc[i][3];
        *(float4*)&out[(size_t)(m0 + ty*4 + i) * 128 + n0 + tx*4] = r;
    }
}

// ---------------------------------------------------------------------------
extern "C" void kernel_launch(void* const* d_in, const int* in_sizes, int n_in,
                              void* d_out, int out_size)
{
    const float* pair   = (const float*)d_in[0];
    const int*   mask   = (const int*)d_in[1];
    const float* ln_w   = (const float*)d_in[2];
    const float* ln_b   = (const float*)d_in[3];
    const float* w_bias = (const float*)d_in[4];
    const float* wq     = (const float*)d_in[5];
    const float* wk     = (const float*)d_in[6];
    const float* wv     = (const float*)d_in[7];
    const float* wg     = (const float*)d_in[8];
    const float* wo     = (const float*)d_in[9];
    float* out = (float*)d_out;

    (void)in_sizes; (void)n_in; (void)out_size;

    ln_bias_kernel<<<MM / 8, 256>>>(pair, ln_w, ln_b, w_bias);
    proj_gemm<<<dim3(MM / 64, 8), 256>>>(wq, wk, wv, wg);

    size_t attn_smem = (size_t)ATTN_SMEM_FLOATS * sizeof(float);
    cudaFuncSetAttribute(attn_kernel,
                         cudaFuncAttributeMaxDynamicSharedMemorySize,
                         (int)attn_smem);
    attn_kernel<<<dim3(NN, HH), 512, attn_smem>>>(mask);

    out_gemm<<<dim3(MM / 64, 2), 256>>>(wo, out);
}

// round 4
// speedup vs baseline: 1.6970x; 1.0833x over previous
#include <cuda_runtime.h>
#include <math.h>

#define NN 384
#define CC 128
#define HH 4
#define DD 32
#define MM (NN*NN)

// Scratch (allocation-free: __device__ globals)
__device__ float d_x[(size_t)MM*CC];      // layernormed pair
__device__ float d_y[(size_t)MM*512];     // [q|k|v|g] concatenated, q pre-scaled
__device__ float d_bias[(size_t)HH*MM];   // bias[h, q, k]
__device__ float d_o[(size_t)MM*CC];      // attention output [b,n,h*32+d]

// ---- packed f32x2 helpers (FFMA2: 2 fp32 MACs per fma-pipe instruction) ----
__device__ __forceinline__ void fma2(unsigned long long& d,
                                     unsigned long long a,
                                     unsigned long long b) {
    asm("fma.rn.f32x2 %0, %1, %2, %0;" : "+l"(d) : "l"(a), "l"(b));
}
__device__ __forceinline__ unsigned long long pack2(float lo, float hi) {
    unsigned long long r;
    asm("mov.b64 %0, {%1, %2};" : "=l"(r) : "f"(lo), "f"(hi));
    return r;
}
__device__ __forceinline__ float2 unpack2(unsigned long long v) {
    float2 r;
    asm("mov.b64 {%0, %1}, %2;" : "=f"(r.x), "=f"(r.y) : "l"(v));
    return r;
}

// ---------------------------------------------------------------------------
// Kernel 1: LayerNorm + pair bias. One warp per row (128 channels, 4/lane).
// ---------------------------------------------------------------------------
__global__ __launch_bounds__(256) void ln_bias_kernel(
    const float* __restrict__ pair,
    const float* __restrict__ ln_w,
    const float* __restrict__ ln_b,
    const float* __restrict__ w_bias)
{
    int warp = threadIdx.x >> 5, lane = threadIdx.x & 31;
    int r = blockIdx.x * 8 + warp;
    if (r >= MM) return;

    float4 v = ((const float4*)(pair + (size_t)r * CC))[lane];
    float s  = v.x + v.y + v.z + v.w;
    float sq = v.x*v.x + v.y*v.y + v.z*v.z + v.w*v.w;
    #pragma unroll
    for (int o = 16; o; o >>= 1) {
        s  += __shfl_xor_sync(0xffffffffu, s,  o);
        sq += __shfl_xor_sync(0xffffffffu, sq, o);
    }
    float mean = s * (1.0f / CC);
    float var  = sq * (1.0f / CC) - mean * mean;
    float inv  = rsqrtf(var + 1e-5f);

    float4 w = ((const float4*)ln_w)[lane];
    float4 b = ((const float4*)ln_b)[lane];
    float4 xn;
    xn.x = (v.x - mean) * inv * w.x + b.x;
    xn.y = (v.y - mean) * inv * w.y + b.y;
    xn.z = (v.z - mean) * inv * w.z + b.z;
    xn.w = (v.w - mean) * inv * w.w + b.w;
    ((float4*)(d_x + (size_t)r * CC))[lane] = xn;

    float accb0 = 0.f, accb1 = 0.f, accb2 = 0.f, accb3 = 0.f;
    float xv[4] = {xn.x, xn.y, xn.z, xn.w};
    #pragma unroll
    for (int i = 0; i < 4; i++) {
        float4 wb = ((const float4*)w_bias)[lane * 4 + i];
        accb0 += xv[i] * wb.x;
        accb1 += xv[i] * wb.y;
        accb2 += xv[i] * wb.z;
        accb3 += xv[i] * wb.w;
    }
    #pragma unroll
    for (int o = 16; o; o >>= 1) {
        accb0 += __shfl_xor_sync(0xffffffffu, accb0, o);
        accb1 += __shfl_xor_sync(0xffffffffu, accb1, o);
        accb2 += __shfl_xor_sync(0xffffffffu, accb2, o);
        accb3 += __shfl_xor_sync(0xffffffffu, accb3, o);
    }
    if (lane == 0) {
        d_bias[(size_t)0 * MM + r] = accb0;
        d_bias[(size_t)1 * MM + r] = accb1;
        d_bias[(size_t)2 * MM + r] = accb2;
        d_bias[(size_t)3 * MM + r] = accb3;
    }
}

// ---------------------------------------------------------------------------
// Kernel 2: projections Y[M,512] = X[M,128] @ [wq|wk|wv|wg]. 64x64x64 tiles.
// FFMA2 inner loop: accumulators packed along n, B pairs loaded as b64.
// ---------------------------------------------------------------------------
__global__ __launch_bounds__(256) void proj_gemm(
    const float* __restrict__ wq, const float* __restrict__ wk,
    const float* __restrict__ wv, const float* __restrict__ wg)
{
    __shared__ float As[64][64];
    __shared__ float Bs[64][64];

    int m0 = blockIdx.x * 64;
    int jb = blockIdx.y * 64;
    int sel = jb >> 7;
    const float* w = (sel == 0) ? wq : (sel == 1) ? wk : (sel == 2) ? wv : wg;
    int jbase = jb & 127;

    int tx = threadIdx.x & 15, ty = threadIdx.x >> 4;
    unsigned long long acc2[4][2] = {};

    for (int kk = 0; kk < 128; kk += 64) {
        #pragma unroll
        for (int i = 0; i < 4; i++) {
            int idx = threadIdx.x + i * 256;
            int row = idx >> 4, c4 = (idx & 15) * 4;
            *(float4*)&As[row][c4] =
                *(const float4*)&d_x[(size_t)(m0 + row) * 128 + kk + c4];
            *(float4*)&Bs[row][c4] =
                *(const float4*)&w[(size_t)(kk + row) * 128 + jbase + c4];
        }
        __syncthreads();
        #pragma unroll 8
        for (int k = 0; k < 64; k++) {
            ulonglong2 b2 = *(const ulonglong2*)&Bs[k][tx * 4];
            #pragma unroll
            for (int m = 0; m < 4; m++) {
                float a = As[ty * 4 + m][k];
                unsigned long long a2 = pack2(a, a);
                fma2(acc2[m][0], a2, b2.x);
                fma2(acc2[m][1], a2, b2.y);
            }
        }
        __syncthreads();
    }

    float scale = (sel == 0) ? 0.17677669529663687f : 1.0f;
    #pragma unroll
    for (int m = 0; m < 4; m++) {
        float2 lo = unpack2(acc2[m][0]);
        float2 hi = unpack2(acc2[m][1]);
        float4 r;
        r.x = lo.x * scale; r.y = lo.y * scale;
        r.z = hi.x * scale; r.w = hi.y * scale;
        *(float4*)&d_y[(size_t)(m0 + ty*4 + m) * 512 + jb + tx*4] = r;
    }
}

// ---------------------------------------------------------------------------
// Kernel 3: attention per (b,h), register-blocked, FFMA2 inner loops.
// 512 threads = 16 warps; each warp owns 24 queries in 6 groups of 4.
// ---------------------------------------------------------------------------
#define SM_KS   0                       // [384][33] = 12672
#define SM_VT   12672                   // [32][388] = 12416
#define SM_MSK  25088                   // [384]
#define SM_QS   25472                   // [16][4*33] = 2112
#define SM_PS   27584                   // [16][4*388] = 24832
#define ATTN_SMEM_FLOATS 52416

__global__ __launch_bounds__(512) void attn_kernel(const int* __restrict__ mask)
{
    extern __shared__ float sm[];
    float* Ks  = sm + SM_KS;
    float* Vt  = sm + SM_VT;
    float* Msk = sm + SM_MSK;

    int b = blockIdx.x, h = blockIdx.y;
    int tid = threadIdx.x, lane = tid & 31, w = tid >> 5;
    const float* Yb = d_y + (size_t)b * (NN * 512);

    for (int idx = tid; idx < NN * 32; idx += 512) {
        int n = idx >> 5, d = idx & 31;
        Ks[n * 33 + d]  = Yb[(size_t)n * 512 + 128 + h * 32 + d];
        Vt[d * 388 + n] = Yb[(size_t)n * 512 + 256 + h * 32 + d];
    }
    for (int k = tid; k < NN; k += 512)
        Msk[k] = (mask[(size_t)b * NN + k] != 0) ? 1.0f : 0.0f;
    __syncthreads();

    float* qs = sm + SM_QS + w * (4 * 33);
    float* ps = sm + SM_PS + w * (4 * 388);

    for (int g = 0; g < 6; g++) {
        int q0 = (g * 16 + w) * 4;

        #pragma unroll
        for (int j = 0; j < 4; j++)
            qs[j * 33 + lane] = Yb[(size_t)(q0 + j) * 512 + h * 32 + lane];
        __syncwarp();

        // Phase A: S[4][384]; acc packed along i-pairs (keys i*32+lane)
        unsigned long long acc2[4][6] = {};

        #pragma unroll 4
        for (int d = 0; d < 32; d++) {
            unsigned long long kv2[6];
            #pragma unroll
            for (int ip = 0; ip < 6; ip++) {
                float k0 = Ks[((2*ip    ) * 32 + lane) * 33 + d];
                float k1 = Ks[((2*ip + 1) * 32 + lane) * 33 + d];
                kv2[ip] = pack2(k0, k1);
            }
            #pragma unroll
            for (int j = 0; j < 4; j++) {
                float qv = qs[j * 33 + d];
                unsigned long long q2 = pack2(qv, qv);
                #pragma unroll
                for (int ip = 0; ip < 6; ip++)
                    fma2(acc2[j][ip], q2, kv2[ip]);
            }
        }

        // Bias + mask + softmax (normalization deferred to output)
        float inv[4];
        #pragma unroll
        for (int j = 0; j < 4; j++) {
            const float* br = d_bias + (size_t)h * MM + (size_t)(q0 + j) * NN;
            float s[12];
            #pragma unroll
            for (int ip = 0; ip < 6; ip++) {
                float2 t = unpack2(acc2[j][ip]);
                s[2*ip]     = t.x;
                s[2*ip + 1] = t.y;
            }
            float mx = -1e30f;
            #pragma unroll
            for (int i = 0; i < 12; i++) {
                int k = i * 32 + lane;
                float v = s[i] + br[k];
                v = (Msk[k] != 0.f) ? v : -1e9f;
                s[i] = v;
                mx = fmaxf(mx, v);
            }
            #pragma unroll
            for (int o = 16; o; o >>= 1)
                mx = fmaxf(mx, __shfl_xor_sync(0xffffffffu, mx, o));
            float sum = 0.f;
            #pragma unroll
            for (int i = 0; i < 12; i++) {
                float e = __expf(s[i] - mx);
                s[i] = e;
                sum += e;
            }
            #pragma unroll
            for (int o = 16; o; o >>= 1)
                sum += __shfl_xor_sync(0xffffffffu, sum, o);
            inv[j] = 1.f / sum;
            #pragma unroll
            for (int i = 0; i < 12; i++)
                ps[j * 388 + i * 32 + lane] = s[i];
        }
        __syncwarp();

        // Phase B: O[4][32] = P[4][384] @ V[384][32]; packed along k (natural pairs)
        unsigned long long o2[4] = {};
        const float* vrow = Vt + lane * 388;
        #pragma unroll 4
        for (int kq = 0; kq < 96; kq++) {
            ulonglong2 v2 = *(const ulonglong2*)&vrow[kq * 4];
            #pragma unroll
            for (int j = 0; j < 4; j++) {
                ulonglong2 p2 = *(const ulonglong2*)&ps[j * 388 + kq * 4];
                fma2(o2[j], p2.x, v2.x);
                fma2(o2[j], p2.y, v2.y);
            }
        }
        float* ob = d_o + ((size_t)b * NN + q0) * CC + h * 32 + lane;
        #pragma unroll
        for (int j = 0; j < 4; j++) {
            float2 t = unpack2(o2[j]);
            ob[j * CC] = (t.x + t.y) * inv[j];
        }
        __syncwarp();
    }
}

// ---------------------------------------------------------------------------
// Kernel 4: out = (o * sigmoid(g)) @ wo. Gate fused into A-tile load. FFMA2.
// ---------------------------------------------------------------------------
__global__ __launch_bounds__(256) void out_gemm(
    const float* __restrict__ wo, float* __restrict__ out)
{
    __shared__ float As[64][64];
    __shared__ float Bs[64][64];

    int m0 = blockIdx.x * 64;
    int n0 = blockIdx.y * 64;
    int tx = threadIdx.x & 15, ty = threadIdx.x >> 4;
    unsigned long long acc2[4][2] = {};

    for (int kk = 0; kk < 128; kk += 64) {
        #pragma unroll
        for (int i = 0; i < 4; i++) {
            int idx = threadIdx.x + i * 256;
            int row = idx >> 4, c4 = (idx & 15) * 4;
            float4 ov = *(const float4*)&d_o[(size_t)(m0 + row) * 128 + kk + c4];
            float4 gv = *(const float4*)&d_y[(size_t)(m0 + row) * 512 + 384 + kk + c4];
            float4 a;
            a.x = ov.x * (1.f / (1.f + __expf(-gv.x)));
            a.y = ov.y * (1.f / (1.f + __expf(-gv.y)));
            a.z = ov.z * (1.f / (1.f + __expf(-gv.z)));
            a.w = ov.w * (1.f / (1.f + __expf(-gv.w)));
            *(float4*)&As[row][c4] = a;
            *(float4*)&Bs[row][c4] =
                *(const float4*)&wo[(size_t)(kk + row) * 128 + n0 + c4];
        }
        __syncthreads();
        #pragma unroll 8
        for (int k = 0; k < 64; k++) {
            ulonglong2 b2 = *(const ulonglong2*)&Bs[k][tx * 4];
            #pragma unroll
            for (int m = 0; m < 4; m++) {
                float a = As[ty * 4 + m][k];
                unsigned long long a2 = pack2(a, a);
                fma2(acc2[m][0], a2, b2.x);
                fma2(acc2[m][1], a2, b2.y);
            }
        }
        __syncthreads();
    }

    #pragma unroll
    for (int m = 0; m < 4; m++) {
        float2 lo = unpack2(acc2[m][0]);
        float2 hi = unpack2(acc2[m][1]);
        float4 r;
        r.x = lo.x; r.y = lo.y; r.z = hi.x; r.w = hi.y;
        *(float4*)&out[(size_t)(m0 + ty*4 + m) * 128 + n0 + tx*4] = r;
    }
}

// ---------------------------------------------------------------------------
extern "C" void kernel_launch(void* const* d_in, const int* in_sizes, int n_in,
                              void* d_out, int out_size)
{
    const float* pair   = (const float*)d_in[0];
    const int*   mask   = (const int*)d_in[1];
    const float* ln_w   = (const float*)d_in[2];
    const float* ln_b   = (const float*)d_in[3];
    const float* w_bias = (const float*)d_in[4];
    const float* wq     = (const float*)d_in[5];
    const float* wk     = (const float*)d_in[6];
    const float* wv     = (const float*)d_in[7];
    const float* wg     = (const float*)d_in[8];
    const float* wo     = (const float*)d_in[9];
    float* out = (float*)d_out;

    (void)in_sizes; (void)n_in; (void)out_size;

    ln_bias_kernel<<<MM / 8, 256>>>(pair, ln_w, ln_b, w_bias);
    proj_gemm<<<dim3(MM / 64, 8), 256>>>(wq, wk, wv, wg);

    size_t attn_smem = (size_t)ATTN_SMEM_FLOATS * sizeof(float);
    cudaFuncSetAttribute(attn_kernel,
                         cudaFuncAttributeMaxDynamicSharedMemorySize,
                         (int)attn_smem);
    attn_kernel<<<dim3(NN, HH), 512, attn_smem>>>(mask);

    out_gemm<<<dim3(MM / 64, 2), 256>>>(wo, out);
}